// round 12
// baseline (speedup 1.0000x reference)
#include <cuda_runtime.h>
#include <cstdint>

#define B_   2
#define S_   2048
#define D_   1024
#define H_   16
#define DK_  64
#define MTOT (B_ * S_)   // 4096

// ---------------------------------------------------------------------------
// Scratch (device globals — no allocation allowed)
// ---------------------------------------------------------------------------
__device__ float g_Q[MTOT * D_];         // plain rows (attention input)
__device__ float g_K[MTOT * D_];         // plain rows
__device__ float g_V[MTOT * D_];         // plain rows
__device__ float g_att[MTOT * D_];       // D col-paired (gemm_out A)
__device__ float g_xr[MTOT * D_];        // x, tf32-rounded, D col-paired
__device__ float g_wr[4 * D_ * D_];      // W, tf32-rounded, k-row-paired

// ---------------------------------------------------------------------------
// Helpers (baseline PTX only)
// ---------------------------------------------------------------------------
__device__ __forceinline__ uint32_t smem_u32(const void* p) {
    uint32_t a;
    asm("{ .reg .u64 t; cvta.to.shared.u64 t, %1; cvt.u32.u64 %0, t; }"
        : "=r"(a) : "l"(p));
    return a;
}
__device__ __forceinline__ void cp16(uint32_t s, const void* g) {
    asm volatile("cp.async.cg.shared.global [%0], [%1], 16;"
                 :: "r"(s), "l"(g) : "memory");
}
#define CP_COMMIT() asm volatile("cp.async.commit_group;" ::: "memory")
#define CP_WAIT(n)  asm volatile("cp.async.wait_group %0;" :: "n"(n) : "memory")

__device__ __forceinline__ uint32_t f2tf(float f) {
    uint32_t u;
    asm("cvt.rna.tf32.f32 %0, %1;" : "=r"(u) : "f"(f));
    return u;
}
__device__ __forceinline__ float rtf(float f) {
    return __uint_as_float(f2tf(f));
}
__device__ __forceinline__ void mma_tf32(float* c, const uint32_t* a,
                                         uint32_t b0, uint32_t b1) {
    asm volatile(
        "mma.sync.aligned.m16n8k8.row.col.f32.tf32.tf32.f32 "
        "{%0,%1,%2,%3}, {%4,%5,%6,%7}, {%8,%9}, {%0,%1,%2,%3};"
        : "+f"(c[0]), "+f"(c[1]), "+f"(c[2]), "+f"(c[3])
        : "r"(a[0]), "r"(a[1]), "r"(a[2]), "r"(a[3]), "r"(b0), "r"(b1));
}

// pair permutation within 8-groups: [0,4,1,5,2,6,3,7]
__device__ __forceinline__ int pairc(int c) {
    int r = c & 7;
    return (c & ~7) + ((r < 4) ? (r << 1) : (((r - 4) << 1) | 1));
}

// ---------------------------------------------------------------------------
// Prep: round to tf32-representable fp32 AND emit paired layouts.
// (Scatter stays within the same 32B sector -> DRAM traffic unchanged.)
// ---------------------------------------------------------------------------
__global__ __launch_bounds__(256) void round_x(const float* __restrict__ in,
                                               float* __restrict__ out)
{
    int i = blockIdx.x * 256 + threadIdx.x;
    float4 v = ((const float4*)in)[i];
    int f0   = i * 4;                       // col ≡ 0 mod 4
    int base = (f0 & ~7) + ((f0 >> 2) & 1); // col-paired positions, stride 2
    out[base + 0] = rtf(v.x);
    out[base + 2] = rtf(v.y);
    out[base + 4] = rtf(v.z);
    out[base + 6] = rtf(v.w);
}

// W[k][n] -> row-paired W' (rows k, k+4 interleaved at element granularity)
__global__ __launch_bounds__(256) void round_w4(const float* __restrict__ w0,
                                                const float* __restrict__ w1,
                                                const float* __restrict__ w2,
                                                const float* __restrict__ w3,
                                                float* __restrict__ dst)
{
    const int by = blockIdx.y;
    const float* src = (by == 0) ? w0 : (by == 1) ? w1 : (by == 2) ? w2 : w3;
    float* out = dst + (size_t)by * D_ * D_;
    int i  = blockIdx.x * 256 + threadIdx.x;
    float4 v = ((const float4*)src)[i];
    int f0 = i * 4;
    int k  = f0 >> 10;           // row (D_=1024)
    int c0 = f0 & 1023;          // col
    size_t rb = (size_t)(k & ~7) * D_ + (size_t)(k & 3) * 2 * D_ + ((k >> 2) & 1);
    out[rb + 2 * (c0 + 0)] = rtf(v.x);
    out[rb + 2 * (c0 + 1)] = rtf(v.y);
    out[rb + 2 * (c0 + 2)] = rtf(v.z);
    out[rb + 2 * (c0 + 3)] = rtf(v.w);
}

// ---------------------------------------------------------------------------
// TF32 GEMM core on paired operands (A col-paired, W row-paired): every
// fragment load is one LDS.64. Epilogue: MODE 0 plain fp32 (final output),
// MODE 1 plain rows + tf32-rounded (Q/K/V for attention).
// ---------------------------------------------------------------------------
#define KCH     32
#define APITCH  40
#define BPITCH  264
#define AFLOATS (128 * APITCH)         // 5120
#define BFLOATS (16 * BPITCH)          // 4224
#define ABYTES  (AFLOATS * 4)
#define BBYTES  (BFLOATS * 4)
#define GSMEM   (2 * (ABYTES + BBYTES)) // 74752 B

template <int MODE>
__device__ __forceinline__ void gemm_body(const float* __restrict__ A,
                                          const float* __restrict__ W,
                                          float* __restrict__ C,
                                          int bx, int by, float* sm)
{
    const int tid  = threadIdx.x;
    const int wid  = tid >> 5;
    const int lane = tid & 31;
    const int g    = lane >> 2;
    const int tig  = lane & 3;
    const int m0w  = (wid >> 2) * 64;
    const int n0w  = (wid & 3) * 32;
    const int N    = D_;

    const float* Ab = A + (size_t)by * 128 * D_;
    const uint32_t sbase = smem_u32(sm);

    float acc[4][4][4];
#pragma unroll
    for (int i = 0; i < 4; i++)
#pragma unroll
        for (int j = 0; j < 4; j++)
#pragma unroll
            for (int q = 0; q < 4; q++) acc[i][j][q] = 0.f;

    const int NC = D_ / KCH;   // 32

    auto copy_chunk = [&](int c, int buf) {
        const float* Ac = Ab + c * KCH;
        const float* Bc = W + (size_t)c * KCH * D_ + 2 * bx * 128;
        uint32_t ab = sbase + (uint32_t)buf * ABYTES;
        uint32_t bb = sbase + 2u * ABYTES + (uint32_t)buf * BBYTES;
#pragma unroll
        for (int p = 0; p < 4; p++) {
            int idx = tid + p * 256;
            int r  = idx >> 3, kq = (idx & 7) << 2;       // A: 128r x 32k
            cp16(ab + (uint32_t)(r * APITCH + kq) * 4, Ac + (size_t)r * D_ + kq);
            int pr = idx >> 6, nq = (idx & 63) << 2;      // B: 16 pair-rows x 256
            cp16(bb + (uint32_t)(pr * BPITCH + nq) * 4,
                 Bc + (size_t)(pr >> 2) * 8 * D_ + (size_t)(pr & 3) * 2 * D_ + nq);
        }
        CP_COMMIT();
    };

    copy_chunk(0, 0);

    for (int c = 0; c < NC; c++) {
        const int buf = c & 1;
        if (c + 1 < NC) { copy_chunk(c + 1, buf ^ 1); CP_WAIT(1); }
        else            { CP_WAIT(0); }
        __syncthreads();

        const float* As = sm + buf * AFLOATS;
        const float* Bs = sm + 2 * AFLOATS + buf * BFLOATS;

#pragma unroll
        for (int kk = 0; kk < KCH; kk += 8) {
            uint32_t a[4][4];
#pragma unroll
            for (int i = 0; i < 4; i++) {
                int r = m0w + 16 * i + g;
                float2 a01 = *(const float2*)&As[r * APITCH + kk + 2 * tig];
                float2 a23 = *(const float2*)&As[(r + 8) * APITCH + kk + 2 * tig];
                a[i][0] = __float_as_uint(a01.x);
                a[i][2] = __float_as_uint(a01.y);
                a[i][1] = __float_as_uint(a23.x);
                a[i][3] = __float_as_uint(a23.y);
            }
#pragma unroll
            for (int j = 0; j < 4; j++) {
                float2 b01 = *(const float2*)
                    &Bs[(kk / 2 + tig) * BPITCH + (n0w + 8 * j + g) * 2];
                uint32_t b0 = __float_as_uint(b01.x);
                uint32_t b1 = __float_as_uint(b01.y);
#pragma unroll
                for (int i = 0; i < 4; i++)
                    mma_tf32(acc[i][j], a[i], b0, b1);
            }
        }
        __syncthreads();
    }

    // Plain, coalesced float2 epilogues (R9 lesson: no scatter here)
#pragma unroll
    for (int i = 0; i < 4; i++) {
        int r0 = by * 128 + m0w + 16 * i + g;
        int r1 = r0 + 8;
#pragma unroll
        for (int j = 0; j < 4; j++) {
            int cc = bx * 128 + n0w + 8 * j + 2 * tig;
            if (MODE == 1) {
                *(float2*)&C[(size_t)r0 * N + cc] =
                    make_float2(rtf(acc[i][j][0]), rtf(acc[i][j][1]));
                *(float2*)&C[(size_t)r1 * N + cc] =
                    make_float2(rtf(acc[i][j][2]), rtf(acc[i][j][3]));
            } else {
                *(float2*)&C[(size_t)r0 * N + cc] =
                    make_float2(acc[i][j][0], acc[i][j][1]);
                *(float2*)&C[(size_t)r1 * N + cc] =
                    make_float2(acc[i][j][2], acc[i][j][3]);
            }
        }
    }
}

// Fused Q/K/V projection: gridDim.x = 24; bx/8 selects weight+destination.
__global__ __launch_bounds__(256, 2) void gemm_qkv(const float* __restrict__ x,
                                                   const float* __restrict__ Wr,
                                                   float* __restrict__ Qo,
                                                   float* __restrict__ Ko,
                                                   float* __restrict__ Vo)
{
    extern __shared__ float sm[];
    const int sel = blockIdx.x >> 3;
    const int bx  = blockIdx.x & 7;
    const float* W = Wr + (size_t)sel * D_ * D_;
    float*       C = (sel == 0) ? Qo : (sel == 1) ? Ko : Vo;
    gemm_body<1>(x, W, C, bx, blockIdx.y, sm);
}

// Output projection: A = g_att (col-paired, written by attn), plain output.
__global__ __launch_bounds__(256, 2) void gemm_out(const float* __restrict__ A,
                                                   const float* __restrict__ W,
                                                   float* __restrict__ C)
{
    extern __shared__ float sm[];
    gemm_body<0>(A, W, C, blockIdx.x, blockIdx.y, sm);
}

// ---------------------------------------------------------------------------
// TF32 tensor-core causal flash attention — R10 body verbatim (183 us),
// EXCEPT the final epilogue writes g_att D-col-paired (once per kernel).
// ---------------------------------------------------------------------------
#define QPITCH  68
#define VPITCH  72
#define OFF_K   8704
#define OFF_V   (8704 + 2 * 4352)
#define KBUF    4352                  // 64*68 floats
#define VBUF    4608                  // 64*72 floats
#define ASMEM   ((OFF_V + 2 * VBUF) * 4)   // 106496 B

__global__ __launch_bounds__(256, 2) void attn_tc(const float* __restrict__ Q,
                                                  const float* __restrict__ K,
                                                  const float* __restrict__ V,
                                                  float* __restrict__ O)
{
    extern __shared__ float sm[];
    float* QP = sm;                 // Q tile, later P tile
    float* Ks = sm + OFF_K;
    float* Vs = sm + OFF_V;

    const int tid  = threadIdx.x;
    const int wid  = tid >> 5;
    const int lane = tid & 31;
    const int g    = lane >> 2;
    const int tig  = lane & 3;

    const int qt = (int)gridDim.x - 1 - (int)blockIdx.x;   // heavy-first
    const int bh = blockIdx.y;
    const int b  = bh >> 4;
    const int h  = bh & 15;

    const size_t base = (size_t)b * S_ * D_ + (size_t)h * DK_;
    const float* Qb = Q + base;
    const float* Kb = K + base;
    const float* Vb = V + base;
    float*       Ob = O + base;

    const int q0  = qt * 128;
    const int r0p = wid * 16 + g;
    const uint32_t sb = smem_u32(sm);

    // ---- load Q tile (group 1) ----
#pragma unroll
    for (int p = 0; p < 8; p++) {
        int idx = tid + p * 256;
        int r = idx >> 4, c = (idx & 15) << 2;
        cp16(sb + (uint32_t)(r * QPITCH + c) * 4,
             Qb + (size_t)(q0 + r) * D_ + c);
    }
    CP_COMMIT();

    auto copy_kv = [&](int t, int buf) {
        const float* Kc = Kb + (size_t)(t * 64) * D_;
        const float* Vc = Vb + (size_t)(t * 64) * D_;
#pragma unroll
        for (int p = 0; p < 4; p++) {
            int idx = tid + p * 256;
            int r = idx >> 4, c = (idx & 15) << 2;
            cp16(sb + (uint32_t)(OFF_K + buf * KBUF + r * QPITCH + c) * 4,
                 Kc + (size_t)r * D_ + c);
            cp16(sb + (uint32_t)(OFF_V + buf * VBUF + r * VPITCH + c) * 4,
                 Vc + (size_t)r * D_ + c);
        }
        CP_COMMIT();
    };

    copy_kv(0, 0);      // group 2

    CP_WAIT(1);         // Q ready (kv0 may be in flight)
    __syncthreads();

    // ---- preload Q fragments (x 1/8 = exponent shift, stays tf32-exact) ----
    uint32_t qf[8][4];
#pragma unroll
    for (int kt = 0; kt < 8; kt++) {
        int kk = kt * 8;
        qf[kt][0] = __float_as_uint(QP[r0p * QPITCH + kk + tig] * 0.125f);
        qf[kt][1] = __float_as_uint(QP[(r0p + 8) * QPITCH + kk + tig] * 0.125f);
        qf[kt][2] = __float_as_uint(QP[r0p * QPITCH + kk + tig + 4] * 0.125f);
        qf[kt][3] = __float_as_uint(QP[(r0p + 8) * QPITCH + kk + tig + 4] * 0.125f);
    }
    __syncthreads();    // all warps read Q before P overwrites the region

    float m0 = -1e30f, m1 = -1e30f, l0 = 0.f, l1 = 0.f;
    float o[8][4];
#pragma unroll
    for (int nt = 0; nt < 8; nt++)
#pragma unroll
        for (int c = 0; c < 4; c++) o[nt][c] = 0.f;

    const int qrow0 = q0 + r0p;
    const int qrow1 = qrow0 + 8;
    const int ntiles = 2 * qt + 2;

    for (int t = 0; t < ntiles; t++) {
        const int buf = t & 1;
        CP_WAIT(0);
        __syncthreads();            // tile t ready; all warps done with t-1
        if (t + 1 < ntiles) copy_kv(t + 1, buf ^ 1);

        const int kofs = buf * KBUF;
        const int vofs = buf * VBUF;
        const int kv0  = t * 64;

        // ---- scores S = Q @ K^T ----
        float sacc[8][4];
#pragma unroll
        for (int nt = 0; nt < 8; nt++)
#pragma unroll
            for (int c = 0; c < 4; c++) sacc[nt][c] = 0.f;

#pragma unroll
        for (int kt = 0; kt < 8; kt++) {
#pragma unroll
            for (int nt = 0; nt < 8; nt++) {
                const float* kb = &Ks[kofs + (nt * 8 + g) * QPITCH + kt * 8 + tig];
                uint32_t b0 = __float_as_uint(kb[0]);
                uint32_t b1 = __float_as_uint(kb[4]);
                mma_tf32(sacc[nt], qf[kt], b0, b1);
            }
        }

        // ---- causal mask (only tiles intersecting the diagonal) ----
        if (kv0 + 63 > q0) {
#pragma unroll
            for (int nt = 0; nt < 8; nt++) {
                int c0 = kv0 + nt * 8 + 2 * tig;
                if (c0     > qrow0) sacc[nt][0] = -1e30f;
                if (c0 + 1 > qrow0) sacc[nt][1] = -1e30f;
                if (c0     > qrow1) sacc[nt][2] = -1e30f;
                if (c0 + 1 > qrow1) sacc[nt][3] = -1e30f;
            }
        }

        // ---- online softmax (rows live on 4-lane groups) ----
        float rmax0 = -1e30f, rmax1 = -1e30f;
#pragma unroll
        for (int nt = 0; nt < 8; nt++) {
            rmax0 = fmaxf(rmax0, fmaxf(sacc[nt][0], sacc[nt][1]));
            rmax1 = fmaxf(rmax1, fmaxf(sacc[nt][2], sacc[nt][3]));
        }
        rmax0 = fmaxf(rmax0, __shfl_xor_sync(0xffffffffu, rmax0, 1));
        rmax0 = fmaxf(rmax0, __shfl_xor_sync(0xffffffffu, rmax0, 2));
        rmax1 = fmaxf(rmax1, __shfl_xor_sync(0xffffffffu, rmax1, 1));
        rmax1 = fmaxf(rmax1, __shfl_xor_sync(0xffffffffu, rmax1, 2));

        float mn0 = fmaxf(m0, rmax0), mn1 = fmaxf(m1, rmax1);
        float corr0 = __expf(m0 - mn0), corr1 = __expf(m1 - mn1);
        m0 = mn0; m1 = mn1;

        float ps0 = 0.f, ps1 = 0.f;
#pragma unroll
        for (int nt = 0; nt < 8; nt++) {
            sacc[nt][0] = __expf(sacc[nt][0] - m0);
            sacc[nt][1] = __expf(sacc[nt][1] - m0);
            sacc[nt][2] = __expf(sacc[nt][2] - m1);
            sacc[nt][3] = __expf(sacc[nt][3] - m1);
            ps0 += sacc[nt][0] + sacc[nt][1];
            ps1 += sacc[nt][2] + sacc[nt][3];
            o[nt][0] *= corr0; o[nt][1] *= corr0;
            o[nt][2] *= corr1; o[nt][3] *= corr1;
        }
        l0 = l0 * corr0 + ps0;
        l1 = l1 * corr1 + ps1;

        // ---- store P to smem, tf32-rounded (warp-private rows) ----
#pragma unroll
        for (int nt = 0; nt < 8; nt++) {
            *(float2*)&QP[r0p * QPITCH + nt * 8 + 2 * tig] =
                make_float2(rtf(sacc[nt][0]), rtf(sacc[nt][1]));
            *(float2*)&QP[(r0p + 8) * QPITCH + nt * 8 + 2 * tig] =
                make_float2(rtf(sacc[nt][2]), rtf(sacc[nt][3]));
        }
        __syncwarp();

        // ---- O += P @ V ----
#pragma unroll
        for (int kt = 0; kt < 8; kt++) {
            uint32_t av[4];
            av[0] = __float_as_uint(QP[r0p * QPITCH + kt * 8 + tig]);
            av[1] = __float_as_uint(QP[(r0p + 8) * QPITCH + kt * 8 + tig]);
            av[2] = __float_as_uint(QP[r0p * QPITCH + kt * 8 + tig + 4]);
            av[3] = __float_as_uint(QP[(r0p + 8) * QPITCH + kt * 8 + tig + 4]);
#pragma unroll
            for (int nt = 0; nt < 8; nt++) {
                const float* vb = &Vs[vofs + (kt * 8 + tig) * VPITCH + nt * 8 + g];
                uint32_t b0 = __float_as_uint(vb[0]);
                uint32_t b1 = __float_as_uint(vb[4 * VPITCH]);
                mma_tf32(o[nt], av, b0, b1);
            }
        }
        // next iteration's leading __syncthreads orders P reads vs next store
    }

    // ---- normalize; write D-col-paired + rounded (gemm_out A layout) ----
    l0 += __shfl_xor_sync(0xffffffffu, l0, 1);
    l0 += __shfl_xor_sync(0xffffffffu, l0, 2);
    l1 += __shfl_xor_sync(0xffffffffu, l1, 1);
    l1 += __shfl_xor_sync(0xffffffffu, l1, 2);
    float inv0 = 1.0f / l0, inv1 = 1.0f / l1;

#pragma unroll
    for (int nt = 0; nt < 8; nt++) {
        int cc = nt * 8 + 2 * tig;
        Ob[(size_t)qrow0 * D_ + pairc(cc)]     = rtf(o[nt][0] * inv0);
        Ob[(size_t)qrow0 * D_ + pairc(cc + 1)] = rtf(o[nt][1] * inv0);
        Ob[(size_t)qrow1 * D_ + pairc(cc)]     = rtf(o[nt][2] * inv1);
        Ob[(size_t)qrow1 * D_ + pairc(cc + 1)] = rtf(o[nt][3] * inv1);
    }
}

// ---------------------------------------------------------------------------
extern "C" void kernel_launch(void* const* d_in, const int* in_sizes, int n_in,
                              void* d_out, int out_size)
{
    (void)in_sizes; (void)n_in; (void)out_size;
    const float* x  = (const float*)d_in[0];
    const float* Wq = (const float*)d_in[1];
    const float* Wk = (const float*)d_in[2];
    const float* Wv = (const float*)d_in[3];
    const float* Wo = (const float*)d_in[4];
    float* out = (float*)d_out;

    float *qp, *kp, *vp, *ap, *xr, *wr;
    cudaGetSymbolAddress((void**)&qp, g_Q);
    cudaGetSymbolAddress((void**)&kp, g_K);
    cudaGetSymbolAddress((void**)&vp, g_V);
    cudaGetSymbolAddress((void**)&ap, g_att);
    cudaGetSymbolAddress((void**)&xr, g_xr);
    cudaGetSymbolAddress((void**)&wr, g_wr);

    cudaFuncSetAttribute(gemm_qkv, cudaFuncAttributeMaxDynamicSharedMemorySize, GSMEM);
    cudaFuncSetAttribute(gemm_out, cudaFuncAttributeMaxDynamicSharedMemorySize, GSMEM);
    cudaFuncSetAttribute(attn_tc,  cudaFuncAttributeMaxDynamicSharedMemorySize, ASMEM);

    round_x<<<(MTOT * D_) / (256 * 4), 256>>>(x, xr);
    round_w4<<<dim3((D_ * D_) / (256 * 4), 4), 256>>>(Wq, Wk, Wv, Wo, wr);

    gemm_qkv<<<dim3(24, MTOT / 128), 256, GSMEM>>>(xr, wr, qp, kp, vp);

    attn_tc<<<dim3(S_ / 128, B_ * H_), 256, ASMEM>>>(qp, kp, vp, ap);

    gemm_out<<<dim3(D_ / 128, MTOT / 128), 256, GSMEM>>>(ap, wr + 3 * (size_t)D_ * D_, out);
}

// round 13
// speedup vs baseline: 1.0145x; 1.0145x over previous
#include <cuda_runtime.h>
#include <cstdint>

#define B_   2
#define S_   2048
#define D_   1024
#define H_   16
#define DK_  64
#define MTOT (B_ * S_)   // 4096

// ---------------------------------------------------------------------------
// Scratch (device globals — no allocation allowed). ALL layouts plain.
// ---------------------------------------------------------------------------
__device__ float g_Q[MTOT * D_];
__device__ float g_K[MTOT * D_];
__device__ float g_V[MTOT * D_];
__device__ float g_att[MTOT * D_];
__device__ float g_xr[MTOT * D_];        // x, tf32-pre-rounded
__device__ float g_wr[4 * D_ * D_];      // Wq,Wk,Wv,Wo, tf32-pre-rounded

// ---------------------------------------------------------------------------
// Helpers (baseline PTX only)
// ---------------------------------------------------------------------------
__device__ __forceinline__ uint32_t smem_u32(const void* p) {
    uint32_t a;
    asm("{ .reg .u64 t; cvta.to.shared.u64 t, %1; cvt.u32.u64 %0, t; }"
        : "=r"(a) : "l"(p));
    return a;
}
__device__ __forceinline__ void cp16(uint32_t s, const void* g) {
    asm volatile("cp.async.cg.shared.global [%0], [%1], 16;"
                 :: "r"(s), "l"(g) : "memory");
}
#define CP_COMMIT() asm volatile("cp.async.commit_group;" ::: "memory")
#define CP_WAIT(n)  asm volatile("cp.async.wait_group %0;" :: "n"(n) : "memory")

__device__ __forceinline__ uint32_t f2tf(float f) {
    uint32_t u;
    asm("cvt.rna.tf32.f32 %0, %1;" : "=r"(u) : "f"(f));
    return u;
}
__device__ __forceinline__ float rtf(float f) {
    return __uint_as_float(f2tf(f));
}
__device__ __forceinline__ void mma_tf32(float* c, const uint32_t* a,
                                         uint32_t b0, uint32_t b1) {
    asm volatile(
        "mma.sync.aligned.m16n8k8.row.col.f32.tf32.tf32.f32 "
        "{%0,%1,%2,%3}, {%4,%5,%6,%7}, {%8,%9}, {%0,%1,%2,%3};"
        : "+f"(c[0]), "+f"(c[1]), "+f"(c[2]), "+f"(c[3])
        : "r"(a[0]), "r"(a[1]), "r"(a[2]), "r"(a[3]), "r"(b0), "r"(b1));
}

// ---------------------------------------------------------------------------
// Prep: round fp32 -> tf32-representable fp32 (rna). Coalesced, plain.
// ---------------------------------------------------------------------------
__global__ __launch_bounds__(256) void round_x(const float* __restrict__ in,
                                               float* __restrict__ out)
{
    int i = blockIdx.x * 256 + threadIdx.x;
    float4 v = ((const float4*)in)[i];
    ((float4*)out)[i] = make_float4(rtf(v.x), rtf(v.y), rtf(v.z), rtf(v.w));
}

__global__ __launch_bounds__(256) void round_w4(const float* __restrict__ w0,
                                                const float* __restrict__ w1,
                                                const float* __restrict__ w2,
                                                const float* __restrict__ w3,
                                                float* __restrict__ dst)
{
    const int by = blockIdx.y;
    const float* src = (by == 0) ? w0 : (by == 1) ? w1 : (by == 2) ? w2 : w3;
    int i = blockIdx.x * 256 + threadIdx.x;
    float4 v = ((const float4*)src)[i];
    ((float4*)(dst + (size_t)by * D_ * D_))[i] =
        make_float4(rtf(v.x), rtf(v.y), rtf(v.z), rtf(v.w));
}

// ---------------------------------------------------------------------------
// TF32 GEMM core. k-dim permutation sigma: mma slot tig <-> physical col
// kk+2*tig, slot tig+4 <-> kk+2*tig+1 (applied to BOTH A cols and B rows,
// so every dot product is unchanged). A-frags become single LDS.64.
// APITCH 40 (=8 mod 32: LDS.64 phases conflict-free), BPITCH 132 (=4 mod 32:
// B rows 2tig/2tig+1 give banks 8*tig+g, conflict-free).
// 3-stage circular cp.async pipeline (R10), one barrier per chunk.
// ---------------------------------------------------------------------------
#define KCH     32
#define APITCH  40
#define BPITCH  132
#define AFLOATS (128 * APITCH)          // 5120
#define BFLOATS (KCH * BPITCH)          // 4224
#define STAGEF  (AFLOATS + BFLOATS)     // 9344 floats
#define STAGEB  (STAGEF * 4)            // 37376 B
#define GSMEM   (3 * STAGEB)            // 112128 B

template <int ROUND>
__device__ __forceinline__ void gemm_body(const float* __restrict__ A,
                                          const float* __restrict__ W,
                                          float* __restrict__ C,
                                          int bx, int by, int N, int K,
                                          float* sm)
{
    const int tid  = threadIdx.x;
    const int wid  = tid >> 5;
    const int lane = tid & 31;
    const int g    = lane >> 2;
    const int tig  = lane & 3;
    const int m0w  = (wid >> 2) * 64;
    const int n0w  = (wid & 3) * 32;

    const float* Ab = A + (size_t)by * 128 * K;
    const float* Wb = W + bx * 128;
    const uint32_t sbase = smem_u32(sm);

    float acc[4][4][4];
#pragma unroll
    for (int i = 0; i < 4; i++)
#pragma unroll
        for (int j = 0; j < 4; j++)
#pragma unroll
            for (int q = 0; q < 4; q++) acc[i][j][q] = 0.f;

    const int NC = K / KCH;   // 32

    auto copy_chunk = [&](int c, int buf) {
        const float* Ac = Ab + c * KCH;
        const float* Bc = Wb + (size_t)c * KCH * N;
        uint32_t ab = sbase + (uint32_t)buf * STAGEB;
        uint32_t bb = ab + (uint32_t)(AFLOATS * 4);
#pragma unroll
        for (int p = 0; p < 4; p++) {
            int idx = tid + p * 256;
            int r  = idx >> 3, kq = (idx & 7) << 2;
            cp16(ab + (uint32_t)(r * APITCH + kq) * 4, Ac + (size_t)r * K + kq);
            int kb = idx >> 5, nq = (idx & 31) << 2;
            cp16(bb + (uint32_t)(kb * BPITCH + nq) * 4, Bc + (size_t)kb * N + nq);
        }
        CP_COMMIT();
    };

    copy_chunk(0, 0);
    copy_chunk(1, 1);

    int bufc = 0;          // compute stage = c % 3
    int bufn = 2;          // copy target  = (c+2) % 3

    for (int c = 0; c < NC; c++) {
        if (c + 1 < NC) { CP_WAIT(1); }
        else            { CP_WAIT(0); }
        __syncthreads();
        if (c + 2 < NC) {
            copy_chunk(c + 2, bufn);
            bufn = (bufn == 2) ? 0 : bufn + 1;
        }

        const float* As = sm + bufc * STAGEF;
        const float* Bs = As + AFLOATS;
        bufc = (bufc == 2) ? 0 : bufc + 1;

#pragma unroll
        for (int kk = 0; kk < KCH; kk += 8) {
            uint32_t a[4][4];
#pragma unroll
            for (int i = 0; i < 4; i++) {
                int r = m0w + 16 * i + g;
                float2 a01 = *(const float2*)&As[r * APITCH + kk + 2 * tig];
                float2 a23 = *(const float2*)&As[(r + 8) * APITCH + kk + 2 * tig];
                a[i][0] = __float_as_uint(a01.x);   // slot k=tig     <-> col kk+2tig
                a[i][2] = __float_as_uint(a01.y);   // slot k=tig+4   <-> col kk+2tig+1
                a[i][1] = __float_as_uint(a23.x);
                a[i][3] = __float_as_uint(a23.y);
            }
#pragma unroll
            for (int j = 0; j < 4; j++) {
                uint32_t b0 = __float_as_uint(Bs[(kk + 2 * tig) * BPITCH + n0w + 8 * j + g]);
                uint32_t b1 = __float_as_uint(Bs[(kk + 2 * tig + 1) * BPITCH + n0w + 8 * j + g]);
#pragma unroll
                for (int i = 0; i < 4; i++)
                    mma_tf32(acc[i][j], a[i], b0, b1);
            }
        }
    }

#pragma unroll
    for (int i = 0; i < 4; i++) {
        int r0 = by * 128 + m0w + 16 * i + g;
#pragma unroll
        for (int j = 0; j < 4; j++) {
            int cc = bx * 128 + n0w + 8 * j + 2 * tig;
            if (ROUND) {
                *(float2*)&C[(size_t)r0 * N + cc] =
                    make_float2(rtf(acc[i][j][0]), rtf(acc[i][j][1]));
                *(float2*)&C[(size_t)(r0 + 8) * N + cc] =
                    make_float2(rtf(acc[i][j][2]), rtf(acc[i][j][3]));
            } else {
                *(float2*)&C[(size_t)r0 * N + cc] =
                    make_float2(acc[i][j][0], acc[i][j][1]);
                *(float2*)&C[(size_t)(r0 + 8) * N + cc] =
                    make_float2(acc[i][j][2], acc[i][j][3]);
            }
        }
    }
}

// Fused Q/K/V projection: gridDim.x = 24; bx/8 selects weight+destination.
__global__ __launch_bounds__(256, 2) void gemm_qkv(const float* __restrict__ x,
                                                   const float* __restrict__ Wr,
                                                   float* __restrict__ Qo,
                                                   float* __restrict__ Ko,
                                                   float* __restrict__ Vo)
{
    extern __shared__ float sm[];
    const int sel = blockIdx.x >> 3;
    const int bx  = blockIdx.x & 7;
    const float* W = Wr + (size_t)sel * D_ * D_;
    float*       C = (sel == 0) ? Qo : (sel == 1) ? Ko : Vo;
    gemm_body<1>(x, W, C, bx, blockIdx.y, D_, D_, sm);
}

// Output projection: full fp32 output (no rounding).
__global__ __launch_bounds__(256, 2) void gemm_out(const float* __restrict__ A,
                                                   const float* __restrict__ W,
                                                   float* __restrict__ C)
{
    extern __shared__ float sm[];
    gemm_body<0>(A, W, C, blockIdx.x, blockIdx.y, D_, D_, sm);
}

// ---------------------------------------------------------------------------
// TF32 causal flash attention. Same sigma trick:
//  - QK contraction (dk): slot tig <-> col kt*8+2tig  => Q frags and K frags
//    load as float2 (K: 128->64 LDS/tile, Q preload halved).
//  - PV contraction (kv): slot tig <-> kv col kt*8+2tig => P A-frags are
//    float2 at the exact addresses softmax stores float2 to (32->16 LDS);
//    V B-frags use rows 2tig/2tig+1 (VPITCH 68 keeps banks 8*tig+g).
// Pitches: Q/K/P = 72 (=8 mod 32, LDS.64-phase conflict-free), V = 68.
// Causal mask indexes kv cols as nt*8+2tig — unchanged by sigma.
// ---------------------------------------------------------------------------
#define QPITCH  72
#define VPITCH  68
#define KBUF    (64 * QPITCH)               // 4608 floats
#define VBUF    (64 * VPITCH)               // 4352 floats
#define OFF_K   (128 * QPITCH)              // 9216
#define OFF_V   (OFF_K + 2 * KBUF)          // 18432
#define ASMEM   ((OFF_V + 2 * VBUF) * 4)    // 108544 B

__global__ __launch_bounds__(256, 2) void attn_tc(const float* __restrict__ Q,
                                                  const float* __restrict__ K,
                                                  const float* __restrict__ V,
                                                  float* __restrict__ O)
{
    extern __shared__ float sm[];
    float* QP = sm;                 // Q tile, later P tile (pitch 72)
    float* Ks = sm + OFF_K;
    float* Vs = sm + OFF_V;

    const int tid  = threadIdx.x;
    const int wid  = tid >> 5;
    const int lane = tid & 31;
    const int g    = lane >> 2;
    const int tig  = lane & 3;

    const int qt = (int)gridDim.x - 1 - (int)blockIdx.x;   // heavy-first
    const int bh = blockIdx.y;
    const int b  = bh >> 4;
    const int h  = bh & 15;

    const size_t base = (size_t)b * S_ * D_ + (size_t)h * DK_;
    const float* Qb = Q + base;
    const float* Kb = K + base;
    const float* Vb = V + base;
    float*       Ob = O + base;

    const int q0  = qt * 128;
    const int r0p = wid * 16 + g;
    const uint32_t sb = smem_u32(sm);

    // ---- load Q tile ----
#pragma unroll
    for (int p = 0; p < 8; p++) {
        int idx = tid + p * 256;
        int r = idx >> 4, c = (idx & 15) << 2;
        cp16(sb + (uint32_t)(r * QPITCH + c) * 4,
             Qb + (size_t)(q0 + r) * D_ + c);
    }
    CP_COMMIT();

    auto copy_kv = [&](int t, int buf) {
        const float* Kc = Kb + (size_t)(t * 64) * D_;
        const float* Vc = Vb + (size_t)(t * 64) * D_;
#pragma unroll
        for (int p = 0; p < 4; p++) {
            int idx = tid + p * 256;
            int r = idx >> 4, c = (idx & 15) << 2;
            cp16(sb + (uint32_t)(OFF_K + buf * KBUF + r * QPITCH + c) * 4,
                 Kc + (size_t)r * D_ + c);
            cp16(sb + (uint32_t)(OFF_V + buf * VBUF + r * VPITCH + c) * 4,
                 Vc + (size_t)r * D_ + c);
        }
        CP_COMMIT();
    };

    copy_kv(0, 0);

    CP_WAIT(1);         // Q ready (kv0 may be in flight)
    __syncthreads();

    // ---- preload Q fragments under sigma (x 1/8 exact), float2 loads ----
    uint32_t qf[8][4];
#pragma unroll
    for (int kt = 0; kt < 8; kt++) {
        int kk = kt * 8 + 2 * tig;
        float2 q01 = *(const float2*)&QP[r0p * QPITCH + kk];
        float2 q23 = *(const float2*)&QP[(r0p + 8) * QPITCH + kk];
        qf[kt][0] = __float_as_uint(q01.x * 0.125f);   // slot tig   <-> col 2tig
        qf[kt][2] = __float_as_uint(q01.y * 0.125f);   // slot tig+4 <-> col 2tig+1
        qf[kt][1] = __float_as_uint(q23.x * 0.125f);
        qf[kt][3] = __float_as_uint(q23.y * 0.125f);
    }
    __syncthreads();    // all warps read Q before P overwrites the region

    float m0 = -1e30f, m1 = -1e30f, l0 = 0.f, l1 = 0.f;
    float o[8][4];
#pragma unroll
    for (int nt = 0; nt < 8; nt++)
#pragma unroll
        for (int c = 0; c < 4; c++) o[nt][c] = 0.f;

    const int qrow0 = q0 + r0p;
    const int qrow1 = qrow0 + 8;
    const int ntiles = 2 * qt + 2;

    for (int t = 0; t < ntiles; t++) {
        const int buf = t & 1;
        CP_WAIT(0);
        __syncthreads();            // tile t ready; all warps done with t-1
        if (t + 1 < ntiles) copy_kv(t + 1, buf ^ 1);

        const int kofs = buf * KBUF;
        const int vofs = buf * VBUF;
        const int kv0  = t * 64;

        // ---- scores S = Q @ K^T (K frag = one float2 under sigma) ----
        float sacc[8][4];
#pragma unroll
        for (int nt = 0; nt < 8; nt++)
#pragma unroll
            for (int c = 0; c < 4; c++) sacc[nt][c] = 0.f;

#pragma unroll
        for (int kt = 0; kt < 8; kt++) {
#pragma unroll
            for (int nt = 0; nt < 8; nt++) {
                float2 k01 = *(const float2*)
                    &Ks[kofs + (nt * 8 + g) * QPITCH + kt * 8 + 2 * tig];
                mma_tf32(sacc[nt], qf[kt],
                         __float_as_uint(k01.x), __float_as_uint(k01.y));
            }
        }

        // ---- causal mask (kv columns — unaffected by sigma) ----
        if (kv0 + 63 > q0) {
#pragma unroll
            for (int nt = 0; nt < 8; nt++) {
                int c0 = kv0 + nt * 8 + 2 * tig;
                if (c0     > qrow0) sacc[nt][0] = -1e30f;
                if (c0 + 1 > qrow0) sacc[nt][1] = -1e30f;
                if (c0     > qrow1) sacc[nt][2] = -1e30f;
                if (c0 + 1 > qrow1) sacc[nt][3] = -1e30f;
            }
        }

        // ---- online softmax (rows live on 4-lane groups) ----
        float rmax0 = -1e30f, rmax1 = -1e30f;
#pragma unroll
        for (int nt = 0; nt < 8; nt++) {
            rmax0 = fmaxf(rmax0, fmaxf(sacc[nt][0], sacc[nt][1]));
            rmax1 = fmaxf(rmax1, fmaxf(sacc[nt][2], sacc[nt][3]));
        }
        rmax0 = fmaxf(rmax0, __shfl_xor_sync(0xffffffffu, rmax0, 1));
        rmax0 = fmaxf(rmax0, __shfl_xor_sync(0xffffffffu, rmax0, 2));
        rmax1 = fmaxf(rmax1, __shfl_xor_sync(0xffffffffu, rmax1, 1));
        rmax1 = fmaxf(rmax1, __shfl_xor_sync(0xffffffffu, rmax1, 2));

        float mn0 = fmaxf(m0, rmax0), mn1 = fmaxf(m1, rmax1);
        float corr0 = __expf(m0 - mn0), corr1 = __expf(m1 - mn1);
        m0 = mn0; m1 = mn1;

        float ps0 = 0.f, ps1 = 0.f;
#pragma unroll
        for (int nt = 0; nt < 8; nt++) {
            sacc[nt][0] = __expf(sacc[nt][0] - m0);
            sacc[nt][1] = __expf(sacc[nt][1] - m0);
            sacc[nt][2] = __expf(sacc[nt][2] - m1);
            sacc[nt][3] = __expf(sacc[nt][3] - m1);
            ps0 += sacc[nt][0] + sacc[nt][1];
            ps1 += sacc[nt][2] + sacc[nt][3];
            o[nt][0] *= corr0; o[nt][1] *= corr0;
            o[nt][2] *= corr1; o[nt][3] *= corr1;
        }
        l0 = l0 * corr0 + ps0;
        l1 = l1 * corr1 + ps1;

        // ---- store P (tf32-rounded), natural col order, pitch 72 ----
#pragma unroll
        for (int nt = 0; nt < 8; nt++) {
            *(float2*)&QP[r0p * QPITCH + nt * 8 + 2 * tig] =
                make_float2(rtf(sacc[nt][0]), rtf(sacc[nt][1]));
            *(float2*)&QP[(r0p + 8) * QPITCH + nt * 8 + 2 * tig] =
                make_float2(rtf(sacc[nt][2]), rtf(sacc[nt][3]));
        }
        __syncwarp();

        // ---- O += P @ V (P frag = float2; V rows 2tig/2tig+1) ----
#pragma unroll
        for (int kt = 0; kt < 8; kt++) {
            uint32_t av[4];
            float2 p01 = *(const float2*)&QP[r0p * QPITCH + kt * 8 + 2 * tig];
            float2 p23 = *(const float2*)&QP[(r0p + 8) * QPITCH + kt * 8 + 2 * tig];
            av[0] = __float_as_uint(p01.x);   // slot tig   <-> kv 2tig
            av[2] = __float_as_uint(p01.y);   // slot tig+4 <-> kv 2tig+1
            av[1] = __float_as_uint(p23.x);
            av[3] = __float_as_uint(p23.y);
#pragma unroll
            for (int nt = 0; nt < 8; nt++) {
                const float* vb = &Vs[vofs + (kt * 8 + 2 * tig) * VPITCH + nt * 8 + g];
                uint32_t b0 = __float_as_uint(vb[0]);
                uint32_t b1 = __float_as_uint(vb[VPITCH]);
                mma_tf32(o[nt], av, b0, b1);
            }
        }
        // next iteration's leading __syncthreads orders P reads vs next store
    }

    // ---- normalize and write (tf32-rounded for gemm_out) ----
    l0 += __shfl_xor_sync(0xffffffffu, l0, 1);
    l0 += __shfl_xor_sync(0xffffffffu, l0, 2);
    l1 += __shfl_xor_sync(0xffffffffu, l1, 1);
    l1 += __shfl_xor_sync(0xffffffffu, l1, 2);
    float inv0 = 1.0f / l0, inv1 = 1.0f / l1;

#pragma unroll
    for (int nt = 0; nt < 8; nt++) {
        int cc = nt * 8 + 2 * tig;
        *(float2*)&Ob[(size_t)qrow0 * D_ + cc] =
            make_float2(rtf(o[nt][0] * inv0), rtf(o[nt][1] * inv0));
        *(float2*)&Ob[(size_t)qrow1 * D_ + cc] =
            make_float2(rtf(o[nt][2] * inv1), rtf(o[nt][3] * inv1));
    }
}

// ---------------------------------------------------------------------------
extern "C" void kernel_launch(void* const* d_in, const int* in_sizes, int n_in,
                              void* d_out, int out_size)
{
    (void)in_sizes; (void)n_in; (void)out_size;
    const float* x  = (const float*)d_in[0];
    const float* Wq = (const float*)d_in[1];
    const float* Wk = (const float*)d_in[2];
    const float* Wv = (const float*)d_in[3];
    const float* Wo = (const float*)d_in[4];
    float* out = (float*)d_out;

    float *qp, *kp, *vp, *ap, *xr, *wr;
    cudaGetSymbolAddress((void**)&qp, g_Q);
    cudaGetSymbolAddress((void**)&kp, g_K);
    cudaGetSymbolAddress((void**)&vp, g_V);
    cudaGetSymbolAddress((void**)&ap, g_att);
    cudaGetSymbolAddress((void**)&xr, g_xr);
    cudaGetSymbolAddress((void**)&wr, g_wr);

    cudaFuncSetAttribute(gemm_qkv, cudaFuncAttributeMaxDynamicSharedMemorySize, GSMEM);
    cudaFuncSetAttribute(gemm_out, cudaFuncAttributeMaxDynamicSharedMemorySize, GSMEM);
    cudaFuncSetAttribute(attn_tc,  cudaFuncAttributeMaxDynamicSharedMemorySize, ASMEM);

    round_x<<<(MTOT * D_) / (256 * 4), 256>>>(x, xr);
    round_w4<<<dim3((D_ * D_) / (256 * 4), 4), 256>>>(Wq, Wk, Wv, Wo, wr);

    gemm_qkv<<<dim3(24, MTOT / 128), 256, GSMEM>>>(xr, wr, qp, kp, vp);

    attn_tc<<<dim3(S_ / 128, B_ * H_), 256, ASMEM>>>(qp, kp, vp, ap);

    gemm_out<<<dim3(D_ / 128, MTOT / 128), 256, GSMEM>>>(ap, wr + 3 * (size_t)D_ * D_, out);
}

// round 14
// speedup vs baseline: 1.9654x; 1.9372x over previous
#include <cuda_runtime.h>
#include <cuda_fp16.h>
#include <cstdint>

#define B_   2
#define S_   2048
#define D_   1024
#define H_   16
#define DK_  64
#define MTOT (B_ * S_)   // 4096

// ---------------------------------------------------------------------------
// Scratch (device globals — no allocation allowed). All fp16 intermediates.
// ---------------------------------------------------------------------------
__device__ __half g_Q[MTOT * D_];        // pre-scaled by 1/8
__device__ __half g_K[MTOT * D_];
__device__ __half g_V[MTOT * D_];
__device__ __half g_att[MTOT * D_];
__device__ __half g_x16[MTOT * D_];
__device__ __half g_w16[4 * D_ * D_];

// ---------------------------------------------------------------------------
// Helpers (baseline PTX only: cp.async, ldmatrix, mma.m16n8k16.f16)
// ---------------------------------------------------------------------------
__device__ __forceinline__ uint32_t smem_u32(const void* p) {
    uint32_t a;
    asm("{ .reg .u64 t; cvta.to.shared.u64 t, %1; cvt.u32.u64 %0, t; }"
        : "=r"(a) : "l"(p));
    return a;
}
__device__ __forceinline__ void cp16(uint32_t s, const void* g) {
    asm volatile("cp.async.cg.shared.global [%0], [%1], 16;"
                 :: "r"(s), "l"(g) : "memory");
}
#define CP_COMMIT() asm volatile("cp.async.commit_group;" ::: "memory")
#define CP_WAIT(n)  asm volatile("cp.async.wait_group %0;" :: "n"(n) : "memory")

__device__ __forceinline__ void ldsm4(uint32_t* r, uint32_t addr) {
    asm volatile("ldmatrix.sync.aligned.m8n8.x4.shared.b16 {%0,%1,%2,%3}, [%4];"
                 : "=r"(r[0]), "=r"(r[1]), "=r"(r[2]), "=r"(r[3]) : "r"(addr));
}
__device__ __forceinline__ void ldsm4t(uint32_t* r, uint32_t addr) {
    asm volatile("ldmatrix.sync.aligned.m8n8.x4.trans.shared.b16 {%0,%1,%2,%3}, [%4];"
                 : "=r"(r[0]), "=r"(r[1]), "=r"(r[2]), "=r"(r[3]) : "r"(addr));
}
__device__ __forceinline__ void mma_f16(float* c, const uint32_t* a,
                                        uint32_t b0, uint32_t b1) {
    asm volatile(
        "mma.sync.aligned.m16n8k16.row.col.f32.f16.f16.f32 "
        "{%0,%1,%2,%3}, {%4,%5,%6,%7}, {%8,%9}, {%0,%1,%2,%3};"
        : "+f"(c[0]), "+f"(c[1]), "+f"(c[2]), "+f"(c[3])
        : "r"(a[0]), "r"(a[1]), "r"(a[2]), "r"(a[3]), "r"(b0), "r"(b1));
}

// ---------------------------------------------------------------------------
// Prep: fp32 -> fp16 (rn), coalesced half2 output.
// ---------------------------------------------------------------------------
__global__ __launch_bounds__(256) void round_x(const float* __restrict__ in,
                                               __half2* __restrict__ out)
{
    int i = blockIdx.x * 256 + threadIdx.x;
    float4 v = ((const float4*)in)[i];
    out[2 * i + 0] = __floats2half2_rn(v.x, v.y);
    out[2 * i + 1] = __floats2half2_rn(v.z, v.w);
}

__global__ __launch_bounds__(256) void round_w4(const float* __restrict__ w0,
                                                const float* __restrict__ w1,
                                                const float* __restrict__ w2,
                                                const float* __restrict__ w3,
                                                __half2* __restrict__ dst)
{
    const int by = blockIdx.y;
    const float* src = (by == 0) ? w0 : (by == 1) ? w1 : (by == 2) ? w2 : w3;
    int i = blockIdx.x * 256 + threadIdx.x;
    float4 v = ((const float4*)src)[i];
    __half2* out = dst + (size_t)by * (D_ * D_ / 2);
    out[2 * i + 0] = __floats2half2_rn(v.x, v.y);
    out[2 * i + 1] = __floats2half2_rn(v.z, v.w);
}

// ---------------------------------------------------------------------------
// fp16 GEMM: C[M,N] = A[M,K] @ W[K,N]. 128x128 tile, 8 warps (2x4),
// K-chunks of 64, 3-stage cp.async pipeline, one barrier per chunk.
// A frags: ldmatrix.x4 on A [m][k] (pitch 72 halfs — conflict-free).
// B frags: ldmatrix.x4.trans on W [k][n] (pitch 136 halfs — conflict-free).
// MODE 0: plain fp32 output. MODE 1: fp16 output scaled by `scale`.
// ---------------------------------------------------------------------------
#define KCH     64
#define AP      72                       // halfs
#define BP      136                      // halfs
#define AHALFS  (128 * AP)               // 9216
#define BHALFS  (KCH * BP)               // 8704
#define STAGEH  (AHALFS + BHALFS)        // 17920 halfs
#define STAGEB  (STAGEH * 2)             // 35840 B
#define GSMEM   (3 * STAGEB)             // 107520 B

template <int MODE>
__device__ __forceinline__ void gemm_body(const __half* __restrict__ A,
                                          const __half* __restrict__ W,
                                          void* __restrict__ C,
                                          int bx, int by, float scale,
                                          __half* smh)
{
    const int tid  = threadIdx.x;
    const int wid  = tid >> 5;
    const int lane = tid & 31;
    const int g    = lane >> 2;
    const int tig  = lane & 3;
    const int ml   = lane >> 3;          // ldmatrix matrix id
    const int rw   = lane & 7;           // ldmatrix row-in-matrix
    const int m0w  = (wid >> 2) * 64;
    const int n0w  = (wid & 3) * 32;
    const int N    = D_;

    const __half* Ab = A + (size_t)by * 128 * D_;
    const uint32_t sbase = smem_u32(smh);

    float acc[4][4][4];
#pragma unroll
    for (int i = 0; i < 4; i++)
#pragma unroll
        for (int j = 0; j < 4; j++)
#pragma unroll
            for (int q = 0; q < 4; q++) acc[i][j][q] = 0.f;

    const int NC = D_ / KCH;   // 16

    auto copy_chunk = [&](int c, int buf) {
        const __half* Ac = Ab + c * KCH;
        const __half* Bc = W + (size_t)c * KCH * D_ + bx * 128;
        uint32_t ab = sbase + (uint32_t)buf * STAGEB;
        uint32_t bb = ab + AHALFS * 2;
#pragma unroll
        for (int p = 0; p < 4; p++) {
            int idx = tid + p * 256;
            int r   = idx >> 3, seg = (idx & 7) << 3;          // A: 128r x 64h
            cp16(ab + (uint32_t)(r * AP + seg) * 2, Ac + (size_t)r * D_ + seg);
            int kb  = idx >> 4, sg2 = (idx & 15) << 3;         // B: 64k x 128h
            cp16(bb + (uint32_t)(kb * BP + sg2) * 2, Bc + (size_t)kb * D_ + sg2);
        }
        CP_COMMIT();
    };

    copy_chunk(0, 0);
    copy_chunk(1, 1);

    int bufc = 0, bufn = 2;

    for (int c = 0; c < NC; c++) {
        if (c + 1 < NC) { CP_WAIT(1); }
        else            { CP_WAIT(0); }
        __syncthreads();
        if (c + 2 < NC) {
            copy_chunk(c + 2, bufn);
            bufn = (bufn == 2) ? 0 : bufn + 1;
        }

        uint32_t Asb = sbase + (uint32_t)bufc * STAGEB;
        uint32_t Bsb = Asb + AHALFS * 2;
        bufc = (bufc == 2) ? 0 : bufc + 1;

#pragma unroll
        for (int kt = 0; kt < 4; kt++) {
            uint32_t a[4][4];
#pragma unroll
            for (int i = 0; i < 4; i++) {
                int row  = m0w + 16 * i + (ml & 1) * 8 + rw;
                int colh = kt * 16 + ((ml >> 1) & 1) * 8;
                ldsm4(a[i], Asb + (uint32_t)(row * AP + colh) * 2);
            }
#pragma unroll
            for (int jj = 0; jj < 2; jj++) {
                uint32_t bf[4];
                int rowb = kt * 16 + (ml & 1) * 8 + rw;
                int colb = n0w + jj * 16 + ((ml >> 1) & 1) * 8;
                ldsm4t(bf, Bsb + (uint32_t)(rowb * BP + colb) * 2);
#pragma unroll
                for (int i = 0; i < 4; i++) {
                    mma_f16(acc[i][2 * jj + 0], a[i], bf[0], bf[1]);
                    mma_f16(acc[i][2 * jj + 1], a[i], bf[2], bf[3]);
                }
            }
        }
    }

#pragma unroll
    for (int i = 0; i < 4; i++) {
        int r0 = by * 128 + m0w + 16 * i + g;
        int r1 = r0 + 8;
#pragma unroll
        for (int j = 0; j < 4; j++) {
            int cc = bx * 128 + n0w + 8 * j + 2 * tig;
            if (MODE == 1) {
                __half2* C2 = (__half2*)C;
                C2[(size_t)r0 * (N / 2) + cc / 2] =
                    __floats2half2_rn(acc[i][j][0] * scale, acc[i][j][1] * scale);
                C2[(size_t)r1 * (N / 2) + cc / 2] =
                    __floats2half2_rn(acc[i][j][2] * scale, acc[i][j][3] * scale);
            } else {
                float* Cf = (float*)C;
                *(float2*)&Cf[(size_t)r0 * N + cc] =
                    make_float2(acc[i][j][0], acc[i][j][1]);
                *(float2*)&Cf[(size_t)r1 * N + cc] =
                    make_float2(acc[i][j][2], acc[i][j][3]);
            }
        }
    }
}

// Fused Q/K/V projection. Q (sel 0) pre-scaled by 1/8 (exact exponent shift).
__global__ __launch_bounds__(256, 2) void gemm_qkv(const __half* __restrict__ x,
                                                   const __half* __restrict__ Wr,
                                                   __half* __restrict__ Qo,
                                                   __half* __restrict__ Ko,
                                                   __half* __restrict__ Vo)
{
    extern __shared__ __half smh[];
    const int sel = blockIdx.x >> 3;
    const int bx  = blockIdx.x & 7;
    const __half* W = Wr + (size_t)sel * D_ * D_;
    __half* Cd = (sel == 0) ? Qo : (sel == 1) ? Ko : Vo;
    float scale = (sel == 0) ? 0.125f : 1.0f;
    gemm_body<1>(x, W, Cd, bx, blockIdx.y, scale, smh);
}

__global__ __launch_bounds__(256, 2) void gemm_out(const __half* __restrict__ A,
                                                   const __half* __restrict__ W,
                                                   float* __restrict__ C)
{
    extern __shared__ __half smh[];
    gemm_body<0>(A, W, C, blockIdx.x, blockIdx.y, 1.0f, smh);
}

// ---------------------------------------------------------------------------
// fp16 causal flash attention. 128 q/CTA, 8 warps x 16 rows, 64-kv tiles,
// double-buffered cp.async. All fragments via ldmatrix (V transposed by
// .trans — no layout games). Softmax fp32 on accumulators; P stored fp16
// (the rounding). Output fp16 for gemm_out.
// Pitch 72 halfs everywhere (144 B: ldmatrix rows land on all 32 banks).
// ---------------------------------------------------------------------------
#define QP_    72
#define QHALFS (128 * QP_)               // 9216
#define KVBUF  (64 * QP_)                // 4608
#define OFF_K  QHALFS                    // 9216
#define OFF_V  (OFF_K + 2 * KVBUF)       // 18432
#define ASMEM  ((OFF_V + 2 * KVBUF) * 2) // 55296 B

__global__ __launch_bounds__(256, 2) void attn_tc(const __half* __restrict__ Q,
                                                  const __half* __restrict__ K,
                                                  const __half* __restrict__ V,
                                                  __half* __restrict__ O)
{
    extern __shared__ __half smh[];
    __half* QP = smh;                    // Q tile, later P tile

    const int tid  = threadIdx.x;
    const int wid  = tid >> 5;
    const int lane = tid & 31;
    const int g    = lane >> 2;
    const int tig  = lane & 3;
    const int ml   = lane >> 3;
    const int rw   = lane & 7;

    const int qt = (int)gridDim.x - 1 - (int)blockIdx.x;   // heavy-first
    const int bh = blockIdx.y;
    const int b  = bh >> 4;
    const int h  = bh & 15;

    const size_t base = (size_t)b * S_ * D_ + (size_t)h * DK_;
    const __half* Qb = Q + base;
    const __half* Kb = K + base;
    const __half* Vb = V + base;
    __half*       Ob = O + base;

    const int q0  = qt * 128;
    const int r0p = wid * 16 + g;
    const uint32_t sb = smem_u32(smh);

    // ---- load Q tile (1024 cp16) ----
#pragma unroll
    for (int p = 0; p < 4; p++) {
        int idx = tid + p * 256;
        int r = idx >> 3, seg = (idx & 7) << 3;
        cp16(sb + (uint32_t)(r * QP_ + seg) * 2,
             Qb + (size_t)(q0 + r) * D_ + seg);
    }
    CP_COMMIT();

    auto copy_kv = [&](int t, int buf) {
        const __half* Kc = Kb + (size_t)(t * 64) * D_;
        const __half* Vc = Vb + (size_t)(t * 64) * D_;
#pragma unroll
        for (int p = 0; p < 2; p++) {
            int idx = tid + p * 256;
            int r = idx >> 3, seg = (idx & 7) << 3;
            cp16(sb + (uint32_t)(OFF_K + buf * KVBUF + r * QP_ + seg) * 2,
                 Kc + (size_t)r * D_ + seg);
            cp16(sb + (uint32_t)(OFF_V + buf * KVBUF + r * QP_ + seg) * 2,
                 Vc + (size_t)r * D_ + seg);
        }
        CP_COMMIT();
    };

    copy_kv(0, 0);

    CP_WAIT(1);
    __syncthreads();

    // ---- preload Q A-fragments (Q already pre-scaled by 1/8) ----
    uint32_t qf[4][4];
#pragma unroll
    for (int kt = 0; kt < 4; kt++) {
        int row  = wid * 16 + (ml & 1) * 8 + rw;
        int colh = kt * 16 + ((ml >> 1) & 1) * 8;
        ldsm4(qf[kt], sb + (uint32_t)(row * QP_ + colh) * 2);
    }
    __syncthreads();    // all warps read Q before P overwrites region

    float m0 = -1e30f, m1 = -1e30f, l0 = 0.f, l1 = 0.f;
    float o[8][4];
#pragma unroll
    for (int nt = 0; nt < 8; nt++)
#pragma unroll
        for (int c = 0; c < 4; c++) o[nt][c] = 0.f;

    const int qrow0 = q0 + r0p;
    const int qrow1 = qrow0 + 8;
    const int ntiles = 2 * qt + 2;

    for (int t = 0; t < ntiles; t++) {
        const int buf = t & 1;
        CP_WAIT(0);
        __syncthreads();            // tile t ready; all warps done with t-1
        if (t + 1 < ntiles) copy_kv(t + 1, buf ^ 1);

        const int kofs = OFF_K + buf * KVBUF;
        const int vofs = OFF_V + buf * KVBUF;
        const int kv0  = t * 64;

        // ---- scores S = (Q/8) @ K^T ----
        float sacc[8][4];
#pragma unroll
        for (int nt = 0; nt < 8; nt++)
#pragma unroll
            for (int c = 0; c < 4; c++) sacc[nt][c] = 0.f;

#pragma unroll
        for (int kt = 0; kt < 4; kt++) {
#pragma unroll
            for (int np = 0; np < 4; np++) {
                uint32_t bf[4];
                int rowb = np * 16 + ((ml >> 1) & 1) * 8 + rw;   // kv rows (n)
                int colb = kt * 16 + (ml & 1) * 8;               // dk (k)
                ldsm4(bf, sb + (uint32_t)(kofs + rowb * QP_ + colb) * 2);
                mma_f16(sacc[2 * np + 0], qf[kt], bf[0], bf[1]);
                mma_f16(sacc[2 * np + 1], qf[kt], bf[2], bf[3]);
            }
        }

        // ---- causal mask (kv columns) ----
        if (kv0 + 63 > q0) {
#pragma unroll
            for (int nt = 0; nt < 8; nt++) {
                int c0 = kv0 + nt * 8 + 2 * tig;
                if (c0     > qrow0) sacc[nt][0] = -1e30f;
                if (c0 + 1 > qrow0) sacc[nt][1] = -1e30f;
                if (c0     > qrow1) sacc[nt][2] = -1e30f;
                if (c0 + 1 > qrow1) sacc[nt][3] = -1e30f;
            }
        }

        // ---- online softmax (rows on 4-lane groups) ----
        float rmax0 = -1e30f, rmax1 = -1e30f;
#pragma unroll
        for (int nt = 0; nt < 8; nt++) {
            rmax0 = fmaxf(rmax0, fmaxf(sacc[nt][0], sacc[nt][1]));
            rmax1 = fmaxf(rmax1, fmaxf(sacc[nt][2], sacc[nt][3]));
        }
        rmax0 = fmaxf(rmax0, __shfl_xor_sync(0xffffffffu, rmax0, 1));
        rmax0 = fmaxf(rmax0, __shfl_xor_sync(0xffffffffu, rmax0, 2));
        rmax1 = fmaxf(rmax1, __shfl_xor_sync(0xffffffffu, rmax1, 1));
        rmax1 = fmaxf(rmax1, __shfl_xor_sync(0xffffffffu, rmax1, 2));

        float mn0 = fmaxf(m0, rmax0), mn1 = fmaxf(m1, rmax1);
        float corr0 = __expf(m0 - mn0), corr1 = __expf(m1 - mn1);
        m0 = mn0; m1 = mn1;

        float ps0 = 0.f, ps1 = 0.f;
#pragma unroll
        for (int nt = 0; nt < 8; nt++) {
            sacc[nt][0] = __expf(sacc[nt][0] - m0);
            sacc[nt][1] = __expf(sacc[nt][1] - m0);
            sacc[nt][2] = __expf(sacc[nt][2] - m1);
            sacc[nt][3] = __expf(sacc[nt][3] - m1);
            ps0 += sacc[nt][0] + sacc[nt][1];
            ps1 += sacc[nt][2] + sacc[nt][3];
            o[nt][0] *= corr0; o[nt][1] *= corr0;
            o[nt][2] *= corr1; o[nt][3] *= corr1;
        }
        l0 = l0 * corr0 + ps0;
        l1 = l1 * corr1 + ps1;

        // ---- store P as fp16 (the rounding), warp-private rows ----
#pragma unroll
        for (int nt = 0; nt < 8; nt++) {
            *(__half2*)&QP[r0p * QP_ + nt * 8 + 2 * tig] =
                __floats2half2_rn(sacc[nt][0], sacc[nt][1]);
            *(__half2*)&QP[(r0p + 8) * QP_ + nt * 8 + 2 * tig] =
                __floats2half2_rn(sacc[nt][2], sacc[nt][3]);
        }
        __syncwarp();

        // ---- O += P @ V (V transposed by ldmatrix.trans) ----
#pragma unroll
        for (int kt = 0; kt < 4; kt++) {
            uint32_t av[4];
            int rowp = wid * 16 + (ml & 1) * 8 + rw;
            int colp = kt * 16 + ((ml >> 1) & 1) * 8;
            ldsm4(av, sb + (uint32_t)(rowp * QP_ + colp) * 2);
#pragma unroll
            for (int np = 0; np < 4; np++) {
                uint32_t bf[4];
                int rowv = kt * 16 + (ml & 1) * 8 + rw;          // kv (k)
                int colv = np * 16 + ((ml >> 1) & 1) * 8;        // dk (n)
                ldsm4t(bf, sb + (uint32_t)(vofs + rowv * QP_ + colv) * 2);
                mma_f16(o[2 * np + 0], av, bf[0], bf[1]);
                mma_f16(o[2 * np + 1], av, bf[2], bf[3]);
            }
        }
    }

    // ---- normalize and write fp16 (gemm_out A operand) ----
    l0 += __shfl_xor_sync(0xffffffffu, l0, 1);
    l0 += __shfl_xor_sync(0xffffffffu, l0, 2);
    l1 += __shfl_xor_sync(0xffffffffu, l1, 1);
    l1 += __shfl_xor_sync(0xffffffffu, l1, 2);
    float inv0 = 1.0f / l0, inv1 = 1.0f / l1;

#pragma unroll
    for (int nt = 0; nt < 8; nt++) {
        int cc = nt * 8 + 2 * tig;
        *(__half2*)&Ob[(size_t)qrow0 * D_ + cc] =
            __floats2half2_rn(o[nt][0] * inv0, o[nt][1] * inv0);
        *(__half2*)&Ob[(size_t)qrow1 * D_ + cc] =
            __floats2half2_rn(o[nt][2] * inv1, o[nt][3] * inv1);
    }
}

// ---------------------------------------------------------------------------
extern "C" void kernel_launch(void* const* d_in, const int* in_sizes, int n_in,
                              void* d_out, int out_size)
{
    (void)in_sizes; (void)n_in; (void)out_size;
    const float* x  = (const float*)d_in[0];
    const float* Wq = (const float*)d_in[1];
    const float* Wk = (const float*)d_in[2];
    const float* Wv = (const float*)d_in[3];
    const float* Wo = (const float*)d_in[4];
    float* out = (float*)d_out;

    __half *qp, *kp, *vp, *ap, *xh, *wh;
    cudaGetSymbolAddress((void**)&qp, g_Q);
    cudaGetSymbolAddress((void**)&kp, g_K);
    cudaGetSymbolAddress((void**)&vp, g_V);
    cudaGetSymbolAddress((void**)&ap, g_att);
    cudaGetSymbolAddress((void**)&xh, g_x16);
    cudaGetSymbolAddress((void**)&wh, g_w16);

    cudaFuncSetAttribute(gemm_qkv, cudaFuncAttributeMaxDynamicSharedMemorySize, GSMEM);
    cudaFuncSetAttribute(gemm_out, cudaFuncAttributeMaxDynamicSharedMemorySize, GSMEM);
    cudaFuncSetAttribute(attn_tc,  cudaFuncAttributeMaxDynamicSharedMemorySize, ASMEM);

    round_x<<<(MTOT * D_) / (256 * 4), 256>>>(x, (__half2*)xh);
    round_w4<<<dim3((D_ * D_) / (256 * 4), 4), 256>>>(Wq, Wk, Wv, Wo, (__half2*)wh);

    gemm_qkv<<<dim3(24, MTOT / 128), 256, GSMEM>>>(xh, wh, qp, kp, vp);

    attn_tc<<<dim3(S_ / 128, B_ * H_), 256, ASMEM>>>(qp, kp, vp, ap);

    gemm_out<<<dim3(D_ / 128, MTOT / 128), 256, GSMEM>>>(ap, wh + 3 * (size_t)D_ * D_, out);
}

// round 16
// speedup vs baseline: 2.0632x; 1.0498x over previous
#include <cuda_runtime.h>
#include <cuda_fp16.h>
#include <cstdint>

#define B_   2
#define S_   2048
#define D_   1024
#define H_   16
#define DK_  64
#define MTOT (B_ * S_)   // 4096

// ---------------------------------------------------------------------------
// Scratch (device globals — no allocation allowed). All fp16 intermediates.
// ---------------------------------------------------------------------------
__device__ __half g_Q[MTOT * D_];        // pre-scaled by log2(e)/8
__device__ __half g_K[MTOT * D_];
__device__ __half g_V[MTOT * D_];
__device__ __half g_att[MTOT * D_];
__device__ __half g_x16[MTOT * D_];
__device__ __half g_w16[4 * D_ * D_];

// ---------------------------------------------------------------------------
// Helpers (baseline PTX only: cp.async, ldmatrix, mma.m16n8k16.f16, ex2.f16x2)
// ---------------------------------------------------------------------------
__device__ __forceinline__ uint32_t smem_u32(const void* p) {
    uint32_t a;
    asm("{ .reg .u64 t; cvta.to.shared.u64 t, %1; cvt.u32.u64 %0, t; }"
        : "=r"(a) : "l"(p));
    return a;
}
__device__ __forceinline__ void cp16(uint32_t s, const void* g) {
    asm volatile("cp.async.cg.shared.global [%0], [%1], 16;"
                 :: "r"(s), "l"(g) : "memory");
}
#define CP_COMMIT() asm volatile("cp.async.commit_group;" ::: "memory")
#define CP_WAIT(n)  asm volatile("cp.async.wait_group %0;" :: "n"(n) : "memory")

__device__ __forceinline__ void ldsm4(uint32_t* r, uint32_t addr) {
    asm volatile("ldmatrix.sync.aligned.m8n8.x4.shared.b16 {%0,%1,%2,%3}, [%4];"
                 : "=r"(r[0]), "=r"(r[1]), "=r"(r[2]), "=r"(r[3]) : "r"(addr));
}
__device__ __forceinline__ void ldsm4t(uint32_t* r, uint32_t addr) {
    asm volatile("ldmatrix.sync.aligned.m8n8.x4.trans.shared.b16 {%0,%1,%2,%3}, [%4];"
                 : "=r"(r[0]), "=r"(r[1]), "=r"(r[2]), "=r"(r[3]) : "r"(addr));
}
__device__ __forceinline__ void mma_f16(float* c, const uint32_t* a,
                                        uint32_t b0, uint32_t b1) {
    asm volatile(
        "mma.sync.aligned.m16n8k16.row.col.f32.f16.f16.f32 "
        "{%0,%1,%2,%3}, {%4,%5,%6,%7}, {%8,%9}, {%0,%1,%2,%3};"
        : "+f"(c[0]), "+f"(c[1]), "+f"(c[2]), "+f"(c[3])
        : "r"(a[0]), "r"(a[1]), "r"(a[2]), "r"(a[3]), "r"(b0), "r"(b1));
}
// two fp16 exp2 in one MUFU op (renamed: h2exp2 exists in cuda_fp16.hpp)
__device__ __forceinline__ __half2 hexp2_(__half2 x) {
    uint32_t r, xi = *(uint32_t*)&x;
    asm("ex2.approx.f16x2 %0, %1;" : "=r"(r) : "r"(xi));
    return *(__half2*)&r;
}

// ---------------------------------------------------------------------------
// Prep (single launch): fp32 -> fp16 for x and all 4 weights.
// blocks [0,4096): x ; [4096,8192): weights (1024 blocks each).
// ---------------------------------------------------------------------------
__global__ __launch_bounds__(256) void cvt_all(const float* __restrict__ x,
                                               const float* __restrict__ w0,
                                               const float* __restrict__ w1,
                                               const float* __restrict__ w2,
                                               const float* __restrict__ w3,
                                               __half2* __restrict__ xo,
                                               __half2* __restrict__ wo)
{
    int bid = blockIdx.x;
    const float* src;
    __half2* dst;
    int local;
    if (bid < 4096) {
        src = x; dst = xo; local = bid;
    } else {
        int wsel = (bid - 4096) >> 10;
        src = (wsel == 0) ? w0 : (wsel == 1) ? w1 : (wsel == 2) ? w2 : w3;
        dst = wo + (size_t)wsel * (D_ * D_ / 2);
        local = (bid - 4096) & 1023;
    }
    int i = local * 256 + threadIdx.x;
    float4 v = ((const float4*)src)[i];
    dst[2 * i + 0] = __floats2half2_rn(v.x, v.y);
    dst[2 * i + 1] = __floats2half2_rn(v.z, v.w);
}

// ---------------------------------------------------------------------------
// fp16 GEMM (R13 winner, unchanged): 128x128 tile, 8 warps, K-chunks of 64,
// 3-stage cp.async pipeline. ldmatrix A, ldmatrix.trans B on [k][n] weights.
// MODE 0: fp32 out. MODE 1: fp16 out scaled by `scale`.
// ---------------------------------------------------------------------------
#define KCH     64
#define AP      72
#define BP      136
#define AHALFS  (128 * AP)
#define BHALFS  (KCH * BP)
#define STAGEH  (AHALFS + BHALFS)
#define STAGEB  (STAGEH * 2)
#define GSMEM   (3 * STAGEB)             // 107520 B

template <int MODE>
__device__ __forceinline__ void gemm_body(const __half* __restrict__ A,
                                          const __half* __restrict__ W,
                                          void* __restrict__ C,
                                          int bx, int by, float scale,
                                          __half* smh)
{
    const int tid  = threadIdx.x;
    const int wid  = tid >> 5;
    const int lane = tid & 31;
    const int g    = lane >> 2;
    const int tig  = lane & 3;
    const int ml   = lane >> 3;
    const int rw   = lane & 7;
    const int m0w  = (wid >> 2) * 64;
    const int n0w  = (wid & 3) * 32;
    const int N    = D_;

    const __half* Ab = A + (size_t)by * 128 * D_;
    const uint32_t sbase = smem_u32(smh);

    float acc[4][4][4];
#pragma unroll
    for (int i = 0; i < 4; i++)
#pragma unroll
        for (int j = 0; j < 4; j++)
#pragma unroll
            for (int q = 0; q < 4; q++) acc[i][j][q] = 0.f;

    const int NC = D_ / KCH;   // 16

    auto copy_chunk = [&](int c, int buf) {
        const __half* Ac = Ab + c * KCH;
        const __half* Bc = W + (size_t)c * KCH * D_ + bx * 128;
        uint32_t ab = sbase + (uint32_t)buf * STAGEB;
        uint32_t bb = ab + AHALFS * 2;
#pragma unroll
        for (int p = 0; p < 4; p++) {
            int idx = tid + p * 256;
            int r   = idx >> 3, seg = (idx & 7) << 3;
            cp16(ab + (uint32_t)(r * AP + seg) * 2, Ac + (size_t)r * D_ + seg);
            int kb  = idx >> 4, sg2 = (idx & 15) << 3;
            cp16(bb + (uint32_t)(kb * BP + sg2) * 2, Bc + (size_t)kb * D_ + sg2);
        }
        CP_COMMIT();
    };

    copy_chunk(0, 0);
    copy_chunk(1, 1);

    int bufc = 0, bufn = 2;

    for (int c = 0; c < NC; c++) {
        if (c + 1 < NC) { CP_WAIT(1); }
        else            { CP_WAIT(0); }
        __syncthreads();
        if (c + 2 < NC) {
            copy_chunk(c + 2, bufn);
            bufn = (bufn == 2) ? 0 : bufn + 1;
        }

        uint32_t Asb = sbase + (uint32_t)bufc * STAGEB;
        uint32_t Bsb = Asb + AHALFS * 2;
        bufc = (bufc == 2) ? 0 : bufc + 1;

#pragma unroll
        for (int kt = 0; kt < 4; kt++) {
            uint32_t a[4][4];
#pragma unroll
            for (int i = 0; i < 4; i++) {
                int row  = m0w + 16 * i + (ml & 1) * 8 + rw;
                int colh = kt * 16 + ((ml >> 1) & 1) * 8;
                ldsm4(a[i], Asb + (uint32_t)(row * AP + colh) * 2);
            }
#pragma unroll
            for (int jj = 0; jj < 2; jj++) {
                uint32_t bf[4];
                int rowb = kt * 16 + (ml & 1) * 8 + rw;
                int colb = n0w + jj * 16 + ((ml >> 1) & 1) * 8;
                ldsm4t(bf, Bsb + (uint32_t)(rowb * BP + colb) * 2);
#pragma unroll
                for (int i = 0; i < 4; i++) {
                    mma_f16(acc[i][2 * jj + 0], a[i], bf[0], bf[1]);
                    mma_f16(acc[i][2 * jj + 1], a[i], bf[2], bf[3]);
                }
            }
        }
    }

#pragma unroll
    for (int i = 0; i < 4; i++) {
        int r0 = by * 128 + m0w + 16 * i + g;
        int r1 = r0 + 8;
#pragma unroll
        for (int j = 0; j < 4; j++) {
            int cc = bx * 128 + n0w + 8 * j + 2 * tig;
            if (MODE == 1) {
                __half2* C2 = (__half2*)C;
                C2[(size_t)r0 * (N / 2) + cc / 2] =
                    __floats2half2_rn(acc[i][j][0] * scale, acc[i][j][1] * scale);
                C2[(size_t)r1 * (N / 2) + cc / 2] =
                    __floats2half2_rn(acc[i][j][2] * scale, acc[i][j][3] * scale);
            } else {
                float* Cf = (float*)C;
                *(float2*)&Cf[(size_t)r0 * N + cc] =
                    make_float2(acc[i][j][0], acc[i][j][1]);
                *(float2*)&Cf[(size_t)r1 * N + cc] =
                    make_float2(acc[i][j][2], acc[i][j][3]);
            }
        }
    }
}

// Fused Q/K/V projection. Q pre-scaled by log2(e)/8 -> scores in log2 units.
__global__ __launch_bounds__(256, 2) void gemm_qkv(const __half* __restrict__ x,
                                                   const __half* __restrict__ Wr,
                                                   __half* __restrict__ Qo,
                                                   __half* __restrict__ Ko,
                                                   __half* __restrict__ Vo)
{
    extern __shared__ __half smh[];
    const int sel = blockIdx.x >> 3;
    const int bx  = blockIdx.x & 7;
    const __half* W = Wr + (size_t)sel * D_ * D_;
    __half* Cd = (sel == 0) ? Qo : (sel == 1) ? Ko : Vo;
    float scale = (sel == 0) ? 0.18033688f : 1.0f;   // log2(e)/8
    gemm_body<1>(x, W, Cd, bx, blockIdx.y, scale, smh);
}

__global__ __launch_bounds__(256, 2) void gemm_out(const __half* __restrict__ A,
                                                   const __half* __restrict__ W,
                                                   float* __restrict__ C)
{
    extern __shared__ __half smh[];
    gemm_body<0>(A, W, C, blockIdx.x, blockIdx.y, 1.0f, smh);
}

// ---------------------------------------------------------------------------
// fp16 causal flash attention, exp2-based softmax (scores arrive in log2
// units). Per tile: pack (s-m) pairs to half2, ONE ex2.approx.f16x2 per pair
// produces the fp16 P pair that goes straight to smem; l sums the same fp16
// values (numerator/denominator consistent). Corrections via exp2f.
// ---------------------------------------------------------------------------
#define QP_    72
#define QHALFS (128 * QP_)               // 9216
#define KVBUF  (64 * QP_)                // 4608
#define OFF_K  QHALFS
#define OFF_V  (OFF_K + 2 * KVBUF)
#define ASMEM  ((OFF_V + 2 * KVBUF) * 2) // 55296 B

__global__ __launch_bounds__(256, 2) void attn_tc(const __half* __restrict__ Q,
                                                  const __half* __restrict__ K,
                                                  const __half* __restrict__ V,
                                                  __half* __restrict__ O)
{
    extern __shared__ __half smh[];
    __half* QP = smh;                    // Q tile, later P tile

    const int tid  = threadIdx.x;
    const int wid  = tid >> 5;
    const int lane = tid & 31;
    const int g    = lane >> 2;
    const int tig  = lane & 3;
    const int ml   = lane >> 3;
    const int rw   = lane & 7;

    const int qt = (int)gridDim.x - 1 - (int)blockIdx.x;   // heavy-first
    const int bh = blockIdx.y;
    const int b  = bh >> 4;
    const int h  = bh & 15;

    const size_t base = (size_t)b * S_ * D_ + (size_t)h * DK_;
    const __half* Qb = Q + base;
    const __half* Kb = K + base;
    const __half* Vb = V + base;
    __half*       Ob = O + base;

    const int q0  = qt * 128;
    const int r0p = wid * 16 + g;
    const uint32_t sb = smem_u32(smh);

    // ---- load Q tile ----
#pragma unroll
    for (int p = 0; p < 4; p++) {
        int idx = tid + p * 256;
        int r = idx >> 3, seg = (idx & 7) << 3;
        cp16(sb + (uint32_t)(r * QP_ + seg) * 2,
             Qb + (size_t)(q0 + r) * D_ + seg);
    }
    CP_COMMIT();

    auto copy_kv = [&](int t, int buf) {
        const __half* Kc = Kb + (size_t)(t * 64) * D_;
        const __half* Vc = Vb + (size_t)(t * 64) * D_;
#pragma unroll
        for (int p = 0; p < 2; p++) {
            int idx = tid + p * 256;
            int r = idx >> 3, seg = (idx & 7) << 3;
            cp16(sb + (uint32_t)(OFF_K + buf * KVBUF + r * QP_ + seg) * 2,
                 Kc + (size_t)r * D_ + seg);
            cp16(sb + (uint32_t)(OFF_V + buf * KVBUF + r * QP_ + seg) * 2,
                 Vc + (size_t)r * D_ + seg);
        }
        CP_COMMIT();
    };

    copy_kv(0, 0);

    CP_WAIT(1);
    __syncthreads();

    // ---- preload Q A-fragments (Q pre-scaled by log2e/8) ----
    uint32_t qf[4][4];
#pragma unroll
    for (int kt = 0; kt < 4; kt++) {
        int row  = wid * 16 + (ml & 1) * 8 + rw;
        int colh = kt * 16 + ((ml >> 1) & 1) * 8;
        ldsm4(qf[kt], sb + (uint32_t)(row * QP_ + colh) * 2);
    }
    __syncthreads();    // all warps read Q before P overwrites region

    float m0 = -1e30f, m1 = -1e30f, l0 = 0.f, l1 = 0.f;
    float o[8][4];
#pragma unroll
    for (int nt = 0; nt < 8; nt++)
#pragma unroll
        for (int c = 0; c < 4; c++) o[nt][c] = 0.f;

    const int qrow0 = q0 + r0p;
    const int qrow1 = qrow0 + 8;
    const int ntiles = 2 * qt + 2;

    for (int t = 0; t < ntiles; t++) {
        const int buf = t & 1;
        CP_WAIT(0);
        __syncthreads();            // tile t ready; all warps done with t-1
        if (t + 1 < ntiles) copy_kv(t + 1, buf ^ 1);

        const int kofs = OFF_K + buf * KVBUF;
        const int vofs = OFF_V + buf * KVBUF;
        const int kv0  = t * 64;

        // ---- scores (log2 units) = (Q*log2e/8) @ K^T ----
        float sacc[8][4];
#pragma unroll
        for (int nt = 0; nt < 8; nt++)
#pragma unroll
            for (int c = 0; c < 4; c++) sacc[nt][c] = 0.f;

#pragma unroll
        for (int kt = 0; kt < 4; kt++) {
#pragma unroll
            for (int np = 0; np < 4; np++) {
                uint32_t bf[4];
                int rowb = np * 16 + ((ml >> 1) & 1) * 8 + rw;
                int colb = kt * 16 + (ml & 1) * 8;
                ldsm4(bf, sb + (uint32_t)(kofs + rowb * QP_ + colb) * 2);
                mma_f16(sacc[2 * np + 0], qf[kt], bf[0], bf[1]);
                mma_f16(sacc[2 * np + 1], qf[kt], bf[2], bf[3]);
            }
        }

        // ---- causal mask ----
        if (kv0 + 63 > q0) {
#pragma unroll
            for (int nt = 0; nt < 8; nt++) {
                int c0 = kv0 + nt * 8 + 2 * tig;
                if (c0     > qrow0) sacc[nt][0] = -1e30f;
                if (c0 + 1 > qrow0) sacc[nt][1] = -1e30f;
                if (c0     > qrow1) sacc[nt][2] = -1e30f;
                if (c0 + 1 > qrow1) sacc[nt][3] = -1e30f;
            }
        }

        // ---- online softmax, exp2 f16x2 ----
        float rmax0 = -1e30f, rmax1 = -1e30f;
#pragma unroll
        for (int nt = 0; nt < 8; nt++) {
            rmax0 = fmaxf(rmax0, fmaxf(sacc[nt][0], sacc[nt][1]));
            rmax1 = fmaxf(rmax1, fmaxf(sacc[nt][2], sacc[nt][3]));
        }
        rmax0 = fmaxf(rmax0, __shfl_xor_sync(0xffffffffu, rmax0, 1));
        rmax0 = fmaxf(rmax0, __shfl_xor_sync(0xffffffffu, rmax0, 2));
        rmax1 = fmaxf(rmax1, __shfl_xor_sync(0xffffffffu, rmax1, 1));
        rmax1 = fmaxf(rmax1, __shfl_xor_sync(0xffffffffu, rmax1, 2));

        float mn0 = fmaxf(m0, rmax0), mn1 = fmaxf(m1, rmax1);
        float corr0 = exp2f(m0 - mn0), corr1 = exp2f(m1 - mn1);
        m0 = mn0; m1 = mn1;

        float ps0 = 0.f, ps1 = 0.f;
#pragma unroll
        for (int nt = 0; nt < 8; nt++) {
            __half2 p01 = hexp2_(__floats2half2_rn(sacc[nt][0] - m0,
                                                   sacc[nt][1] - m0));
            __half2 p23 = hexp2_(__floats2half2_rn(sacc[nt][2] - m1,
                                                   sacc[nt][3] - m1));
            // direct fp16 P store (the rounding), warp-private rows
            *(__half2*)&QP[r0p * QP_ + nt * 8 + 2 * tig] = p01;
            *(__half2*)&QP[(r0p + 8) * QP_ + nt * 8 + 2 * tig] = p23;
            float2 f01 = __half22float2(p01);
            float2 f23 = __half22float2(p23);
            ps0 += f01.x + f01.y;
            ps1 += f23.x + f23.y;
            o[nt][0] *= corr0; o[nt][1] *= corr0;
            o[nt][2] *= corr1; o[nt][3] *= corr1;
        }
        l0 = l0 * corr0 + ps0;
        l1 = l1 * corr1 + ps1;
        __syncwarp();

        // ---- O += P @ V (V transposed by ldmatrix.trans) ----
#pragma unroll
        for (int kt = 0; kt < 4; kt++) {
            uint32_t av[4];
            int rowp = wid * 16 + (ml & 1) * 8 + rw;
            int colp = kt * 16 + ((ml >> 1) & 1) * 8;
            ldsm4(av, sb + (uint32_t)(rowp * QP_ + colp) * 2);
#pragma unroll
            for (int np = 0; np < 4; np++) {
                uint32_t bf[4];
                int rowv = kt * 16 + (ml & 1) * 8 + rw;
                int colv = np * 16 + ((ml >> 1) & 1) * 8;
                ldsm4t(bf, sb + (uint32_t)(vofs + rowv * QP_ + colv) * 2);
                mma_f16(o[2 * np + 0], av, bf[0], bf[1]);
                mma_f16(o[2 * np + 1], av, bf[2], bf[3]);
            }
        }
    }

    // ---- normalize and write fp16 ----
    l0 += __shfl_xor_sync(0xffffffffu, l0, 1);
    l0 += __shfl_xor_sync(0xffffffffu, l0, 2);
    l1 += __shfl_xor_sync(0xffffffffu, l1, 1);
    l1 += __shfl_xor_sync(0xffffffffu, l1, 2);
    float inv0 = 1.0f / l0, inv1 = 1.0f / l1;

#pragma unroll
    for (int nt = 0; nt < 8; nt++) {
        int cc = nt * 8 + 2 * tig;
        *(__half2*)&Ob[(size_t)qrow0 * D_ + cc] =
            __floats2half2_rn(o[nt][0] * inv0, o[nt][1] * inv0);
        *(__half2*)&Ob[(size_t)qrow1 * D_ + cc] =
            __floats2half2_rn(o[nt][2] * inv1, o[nt][3] * inv1);
    }
}

// ---------------------------------------------------------------------------
extern "C" void kernel_launch(void* const* d_in, const int* in_sizes, int n_in,
                              void* d_out, int out_size)
{
    (void)in_sizes; (void)n_in; (void)out_size;
    const float* x  = (const float*)d_in[0];
    const float* Wq = (const float*)d_in[1];
    const float* Wk = (const float*)d_in[2];
    const float* Wv = (const float*)d_in[3];
    const float* Wo = (const float*)d_in[4];
    float* out = (float*)d_out;

    __half *qp, *kp, *vp, *ap, *xh, *wh;
    cudaGetSymbolAddress((void**)&qp, g_Q);
    cudaGetSymbolAddress((void**)&kp, g_K);
    cudaGetSymbolAddress((void**)&vp, g_V);
    cudaGetSymbolAddress((void**)&ap, g_att);
    cudaGetSymbolAddress((void**)&xh, g_x16);
    cudaGetSymbolAddress((void**)&wh, g_w16);

    cudaFuncSetAttribute(gemm_qkv, cudaFuncAttributeMaxDynamicSharedMemorySize, GSMEM);
    cudaFuncSetAttribute(gemm_out, cudaFuncAttributeMaxDynamicSharedMemorySize, GSMEM);
    cudaFuncSetAttribute(attn_tc,  cudaFuncAttributeMaxDynamicSharedMemorySize, ASMEM);

    cvt_all<<<8192, 256>>>(x, Wq, Wk, Wv, Wo, (__half2*)xh, (__half2*)wh);

    gemm_qkv<<<dim3(24, MTOT / 128), 256, GSMEM>>>(xh, wh, qp, kp, vp);

    attn_tc<<<dim3(S_ / 128, B_ * H_), 256, ASMEM>>>(qp, kp, vp, ap);

    gemm_out<<<dim3(D_ / 128, MTOT / 128), 256, GSMEM>>>(ap, wh + 3 * (size_t)D_ * D_, out);
}